// round 6
// baseline (speedup 1.0000x reference)
#include <cuda_runtime.h>
#include <math.h>

// Problem shape (fixed by the reference): x[N,K], w[M,K], out[N,M]
#define N_ 1024
#define K_ 256
#define M_ 1024
#define TCTAS 64            // 64x64 transpose tiles: 16 (m) x 4 (k)
#define WPR 4               // warps per row (each covers M_/WPR = 256 m's)

// Scratch (allocs forbidden; __device__ globals are the sanctioned path).
// Writes are idempotent across graph replays (same inputs -> same values),
// so replay reads are deterministic.
__device__ float        g_bT[K_][M_];   // bT[k][m] = |w[m][k]| (1 MB, L2-resident)
__device__ unsigned int g_bmax_bits;    // bits of max|w| (nonneg fp32 orders as uint)
__device__ unsigned int g_done;         // monotone transpose-completion counter

// ---------------------------------------------------------------------------
// ONE kernel, grid = 512 CTAs x 256 threads. Warp g = bid*8+wid handles
// row n = g/4, m-quarter q = g%4. CTAs 0..63 first transpose one 64x64 |w|
// tile into g_bT (all 512 CTAs are co-resident -> spin is deadlock-free).
// Exact pruning: keep k iff a[n,k] + Bmax >= amax_n (fp-monotone => exact).
// No block barriers / no smem on the sweep path: pure warp ops + batched LDG.
// ---------------------------------------------------------------------------
__global__ void __launch_bounds__(256)
tropical_warp_kernel(const float* __restrict__ x,
                     const float* __restrict__ w,
                     float* __restrict__ out) {
    __shared__ float tile[64][65];       // transpose staging only (CTAs < 64)

    const int bid  = blockIdx.x;
    const int tid  = threadIdx.x;
    const int lane = tid & 31;
    const int wid  = tid >> 5;

    const int g = bid * 8 + wid;         // global warp id
    const int n = g >> 2;                // output row
    const int q = g & 3;                 // m-quarter (256 m's)

    // ---- phase 1: full x-row per warp (k = lane*8 + j), row max ----
    const float4 xv0 = reinterpret_cast<const float4*>(x + n * K_ + lane * 8)[0];
    const float4 xv1 = reinterpret_cast<const float4*>(x + n * K_ + lane * 8)[1];
    float av[8];
    av[0] = fabsf(xv0.x); av[1] = fabsf(xv0.y);
    av[2] = fabsf(xv0.z); av[3] = fabsf(xv0.w);
    av[4] = fabsf(xv1.x); av[5] = fabsf(xv1.y);
    av[6] = fabsf(xv1.z); av[7] = fabsf(xv1.w);
    float lmax = av[0];
    #pragma unroll
    for (int j = 1; j < 8; j++) lmax = fmaxf(lmax, av[j]);
    const float amax = __uint_as_float(
        __reduce_max_sync(0xffffffffu, __float_as_uint(lmax)));

    // ---- transpose prologue (CTAs 0..63), overlapped with others' phase 1 ----
    if (bid < TCTAS) {
        const int bm = (bid & 15) * 64;  // m-tile base
        const int bk = (bid >> 4) * 64;  // k-tile base
        const int k4 = tid & 15;         // float4 index along k
        const int m0 = tid >> 4;         // m within tile, step 16
        float wmx = 0.0f;
        #pragma unroll
        for (int i = 0; i < 4; i++) {
            const int m = m0 + i * 16;
            const float4 v = reinterpret_cast<const float4*>(
                                 &w[(bm + m) * K_ + bk])[k4];
            const float a0 = fabsf(v.x), a1 = fabsf(v.y),
                        a2 = fabsf(v.z), a3 = fabsf(v.w);
            tile[4 * k4 + 0][m] = a0;
            tile[4 * k4 + 1][m] = a1;
            tile[4 * k4 + 2][m] = a2;
            tile[4 * k4 + 3][m] = a3;
            wmx = fmaxf(wmx, fmaxf(fmaxf(a0, a1), fmaxf(a2, a3)));
        }
        const unsigned int wmb =
            __reduce_max_sync(0xffffffffu, __float_as_uint(wmx));
        if (lane == 0) atomicMax(&g_bmax_bits, wmb);
        __syncthreads();

        const int m4 = tid & 15;
        const int k0 = tid >> 4;
        #pragma unroll
        for (int i = 0; i < 4; i++) {
            const int k = k0 + i * 16;
            float4 o;
            o.x = tile[k][4 * m4 + 0];
            o.y = tile[k][4 * m4 + 1];
            o.z = tile[k][4 * m4 + 2];
            o.w = tile[k][4 * m4 + 3];
            reinterpret_cast<float4*>(&g_bT[bk + k][bm])[m4] = o;
        }
        __threadfence();                 // release bT + bmax
        __syncthreads();
        if (tid == 0) atomicAdd(&g_done, 1u);
    }

    // ---- wait for all 64 tiles (no-op on graph replays: g_done persists) ----
    if (tid == 0) {
        volatile unsigned int* dp = &g_done;
        while (*dp < TCTAS) { }
        __threadfence();                 // acquire
    }
    __syncthreads();

    const float Bmax =
        __uint_as_float(*(volatile unsigned int*)&g_bmax_bits);

    // ---- exact pruning + sweep (warp-uniform control flow) ----
    const float4* const bbase =
        reinterpret_cast<const float4*>(&g_bT[0][q * (M_ / WPR)]) ;
    // g_bT row stride in float4: M_/4 = 256
    float4 acc0 = make_float4(-INFINITY, -INFINITY, -INFINITY, -INFINITY);
    float4 acc1 = acc0;

    #pragma unroll
    for (int j = 0; j < 8; j++) {
        unsigned int bal =
            __ballot_sync(0xffffffffu, av[j] + Bmax >= amax);  // >= keeps argmax
        while (bal) {
            const int i = __ffs(bal) - 1;
            bal &= bal - 1;
            const float aj = __shfl_sync(0xffffffffu, av[j], i);
            const int   kj = i * 8 + j;
            const float4* bp = bbase + kj * (M_ / 4) + lane;
            const float4 b0 = bp[0];
            const float4 b1 = bp[32];
            acc0.x = fmaxf(acc0.x, aj + b0.x);
            acc0.y = fmaxf(acc0.y, aj + b0.y);
            acc0.z = fmaxf(acc0.z, aj + b0.z);
            acc0.w = fmaxf(acc0.w, aj + b0.w);
            acc1.x = fmaxf(acc1.x, aj + b1.x);
            acc1.y = fmaxf(acc1.y, aj + b1.y);
            acc1.z = fmaxf(acc1.z, aj + b1.z);
            acc1.w = fmaxf(acc1.w, aj + b1.w);
        }
    }

    float4* op = reinterpret_cast<float4*>(out + n * M_ + q * (M_ / WPR)) + lane;
    op[0]  = acc0;
    op[32] = acc1;
}

// ---------------------------------------------------------------------------
extern "C" void kernel_launch(void* const* d_in, const int* in_sizes, int n_in,
                              void* d_out, int out_size) {
    const float* x = (const float*)d_in[0];   // [N, K] fp32
    const float* w = (const float*)d_in[1];   // [M, K] fp32
    float* out     = (float*)d_out;           // [N, M] fp32

    (void)in_sizes; (void)n_in; (void)out_size;

    tropical_warp_kernel<<<N_ * WPR / 8, 256>>>(x, w, out);
}

// round 7
// speedup vs baseline: 1.2083x; 1.2083x over previous
#include <cuda_runtime.h>
#include <math.h>

// Problem shape (fixed by the reference): x[N,K], w[M,K], out[N,M]
#define N_ 1024
#define K_ 256
#define M_ 1024

// Scratch (allocs forbidden; __device__ globals are the sanctioned path).
// Writes are idempotent across graph replays (same inputs -> same values).
__device__ float        g_bT[K_][M_];   // bT[k][m] = |w[m][k]| (1 MB, L2-resident)
__device__ unsigned int g_bmax_bits;    // bits of max|w| (nonneg fp32 orders as uint)

// ---------------------------------------------------------------------------
// Kernel A: abs + transpose of w (float4 both directions), plus Bmax.
// 64x64 tiles: grid = (M/64, K/64) = (16, 4) = 64 blocks, 256 threads.
// ---------------------------------------------------------------------------
__global__ void __launch_bounds__(256)
absT_kernel(const float* __restrict__ w) {
    __shared__ float tile[64][65];       // [k][m], +1 pad

    const int bm   = blockIdx.x * 64;    // m-tile base
    const int bk   = blockIdx.y * 64;    // k-tile base
    const int tid  = threadIdx.x;
    const int lane = tid & 31;

    const int k4 = tid & 15;             // float4 index along k (0..15)
    const int m0 = tid >> 4;             // m within tile (0..15), step 16
    float lmax = 0.0f;
    #pragma unroll
    for (int i = 0; i < 4; i++) {
        const int m = m0 + i * 16;
        const float4 v = reinterpret_cast<const float4*>(
                             &w[(bm + m) * K_ + bk])[k4];
        const float a0 = fabsf(v.x), a1 = fabsf(v.y),
                    a2 = fabsf(v.z), a3 = fabsf(v.w);
        tile[4 * k4 + 0][m] = a0;
        tile[4 * k4 + 1][m] = a1;
        tile[4 * k4 + 2][m] = a2;
        tile[4 * k4 + 3][m] = a3;
        lmax = fmaxf(lmax, fmaxf(fmaxf(a0, a1), fmaxf(a2, a3)));
    }
    const unsigned int wm = __reduce_max_sync(0xffffffffu, __float_as_uint(lmax));
    if (lane == 0) atomicMax(&g_bmax_bits, wm);
    __syncthreads();

    const int m4 = tid & 15;             // float4 index along m (0..15)
    const int k0 = tid >> 4;             // k within tile (0..15), step 16
    #pragma unroll
    for (int i = 0; i < 4; i++) {
        const int k = k0 + i * 16;
        float4 o;
        o.x = tile[k][4 * m4 + 0];
        o.y = tile[k][4 * m4 + 1];
        o.z = tile[k][4 * m4 + 2];
        o.w = tile[k][4 * m4 + 3];
        reinterpret_cast<float4*>(&g_bT[bk + k][bm])[m4] = o;
    }
}

// ---------------------------------------------------------------------------
// Kernel B: grid = 2048 CTAs x 128 threads; warp = (row n, 128-m slice).
// Fully warp-autonomous: no smem, no block barriers, no atomics.
// Exact pruning: keep k iff a[n,k] + Bmax >= amax_n (fp-monotone => exact;
// ">=" keeps the argmax, so at least one candidate always survives).
// ---------------------------------------------------------------------------
__global__ void __launch_bounds__(128)
tropical_sweep_kernel(const float* __restrict__ x,
                      float* __restrict__ out) {
    const int tid   = threadIdx.x;
    const int lane  = tid & 31;
    const int wid   = tid >> 5;
    const int n     = blockIdx.x >> 1;               // output row
    const int slice = ((blockIdx.x & 1) << 2) | wid; // 0..7, 128 m's each

    // ---- full x-row per warp: k = lane*8 + j ----
    const float4* xr = reinterpret_cast<const float4*>(x + n * K_);
    const float4 v0 = xr[lane * 2];
    const float4 v1 = xr[lane * 2 + 1];
    float av[8];
    av[0] = fabsf(v0.x); av[1] = fabsf(v0.y);
    av[2] = fabsf(v0.z); av[3] = fabsf(v0.w);
    av[4] = fabsf(v1.x); av[5] = fabsf(v1.y);
    av[6] = fabsf(v1.z); av[7] = fabsf(v1.w);

    float lmax = av[0];
    #pragma unroll
    for (int j = 1; j < 8; j++) lmax = fmaxf(lmax, av[j]);
    const float amax = __uint_as_float(
        __reduce_max_sync(0xffffffffu, __float_as_uint(lmax)));

    const float Bmax = __uint_as_float(g_bmax_bits);   // written by kernel A
                                                       // (ordered by kernel boundary)

    // ---- exact pruning + sweep over this warp's 128-m slice ----
    const float4* const bbase =
        reinterpret_cast<const float4*>(g_bT) + slice * 32 + lane;
    float4 acc = make_float4(-INFINITY, -INFINITY, -INFINITY, -INFINITY);

    #pragma unroll
    for (int j = 0; j < 8; j++) {
        unsigned int bal =
            __ballot_sync(0xffffffffu, av[j] + Bmax >= amax);
        while (bal) {
            const int i = __ffs(bal) - 1;
            bal &= bal - 1;
            const float aj = __shfl_sync(0xffffffffu, av[j], i);
            const int   kj = i * 8 + j;
            const float4 b = bbase[kj * (M_ / 4)];     // coalesced LDG.128
            acc.x = fmaxf(acc.x, aj + b.x);
            acc.y = fmaxf(acc.y, aj + b.y);
            acc.z = fmaxf(acc.z, aj + b.z);
            acc.w = fmaxf(acc.w, aj + b.w);
        }
    }

    reinterpret_cast<float4*>(out + n * M_)[slice * 32 + lane] = acc;
}

// ---------------------------------------------------------------------------
extern "C" void kernel_launch(void* const* d_in, const int* in_sizes, int n_in,
                              void* d_out, int out_size) {
    const float* x = (const float*)d_in[0];   // [N, K] fp32
    const float* w = (const float*)d_in[1];   // [M, K] fp32
    float* out     = (float*)d_out;           // [N, M] fp32

    (void)in_sizes; (void)n_in; (void)out_size;

    absT_kernel<<<dim3(M_ / 64, K_ / 64), 256>>>(w);
    tropical_sweep_kernel<<<2 * N_, 128>>>(x, out);
}

// round 8
// speedup vs baseline: 1.2119x; 1.0030x over previous
#include <cuda_runtime.h>
#include <math.h>

// Problem shape (fixed by the reference): x[N,K], w[M,K], out[N,M]
#define N_ 1024
#define K_ 256
#define M_ 1024

// Scratch (allocs forbidden; __device__ globals are the sanctioned path).
// All writes are idempotent across graph replays (same inputs -> same values).
__device__ float        g_bT[K_][M_];     // bT[k][m] = |w[m][k]| (1 MB, L2-resident)
__device__ unsigned int g_bmax_bits;      // bits of max|w| (nonneg fp32 orders as uint)
__device__ float2       g_cand[N_][K_];   // per-row compacted {a, bits(k)} pairs
__device__ int          g_cnt[N_];        // per-row candidate count (>=1)

// ---------------------------------------------------------------------------
// Kernel 1: abs + transpose of w (float4 both directions), plus Bmax.
// 64x64 tiles: grid = (16, 4) = 64 blocks, 256 threads.
// ---------------------------------------------------------------------------
__global__ void __launch_bounds__(256)
absT_kernel(const float* __restrict__ w) {
    __shared__ float tile[64][65];        // [k][m], +1 pad

    const int bm   = blockIdx.x * 64;
    const int bk   = blockIdx.y * 64;
    const int tid  = threadIdx.x;
    const int lane = tid & 31;

    const int k4 = tid & 15;
    const int m0 = tid >> 4;
    float lmax = 0.0f;
    #pragma unroll
    for (int i = 0; i < 4; i++) {
        const int m = m0 + i * 16;
        const float4 v = reinterpret_cast<const float4*>(
                             &w[(bm + m) * K_ + bk])[k4];
        const float a0 = fabsf(v.x), a1 = fabsf(v.y),
                    a2 = fabsf(v.z), a3 = fabsf(v.w);
        tile[4 * k4 + 0][m] = a0;
        tile[4 * k4 + 1][m] = a1;
        tile[4 * k4 + 2][m] = a2;
        tile[4 * k4 + 3][m] = a3;
        lmax = fmaxf(lmax, fmaxf(fmaxf(a0, a1), fmaxf(a2, a3)));
    }
    const unsigned int wm = __reduce_max_sync(0xffffffffu, __float_as_uint(lmax));
    if (lane == 0) atomicMax(&g_bmax_bits, wm);
    __syncthreads();

    const int m4 = tid & 15;
    const int k0 = tid >> 4;
    #pragma unroll
    for (int i = 0; i < 4; i++) {
        const int k = k0 + i * 16;
        float4 o;
        o.x = tile[k][4 * m4 + 0];
        o.y = tile[k][4 * m4 + 1];
        o.z = tile[k][4 * m4 + 2];
        o.w = tile[k][4 * m4 + 3];
        reinterpret_cast<float4*>(&g_bT[bk + k][bm])[m4] = o;
    }
}

// ---------------------------------------------------------------------------
// Kernel 2: one warp per row. Exact pruning (keep k iff a+Bmax >= amax;
// fp-monotone => exact, ">=" keeps the argmax so cnt >= 1). Writes the
// compacted candidate list once, so sweep warps never touch x again.
// grid = 256 CTAs x 128 threads (warp w of CTA b owns row b*4+w).
// ---------------------------------------------------------------------------
__global__ void __launch_bounds__(128)
candidates_kernel(const float* __restrict__ x) {
    const int lane = threadIdx.x & 31;
    const int n    = blockIdx.x * 4 + (threadIdx.x >> 5);

    const float4* xr = reinterpret_cast<const float4*>(x + n * K_);
    const float4 v0 = xr[lane * 2];
    const float4 v1 = xr[lane * 2 + 1];
    float av[8];
    av[0] = fabsf(v0.x); av[1] = fabsf(v0.y);
    av[2] = fabsf(v0.z); av[3] = fabsf(v0.w);
    av[4] = fabsf(v1.x); av[5] = fabsf(v1.y);
    av[6] = fabsf(v1.z); av[7] = fabsf(v1.w);

    float lmax = av[0];
    #pragma unroll
    for (int j = 1; j < 8; j++) lmax = fmaxf(lmax, av[j]);
    const float amax = __uint_as_float(
        __reduce_max_sync(0xffffffffu, __float_as_uint(lmax)));
    const float Bmax = __uint_as_float(g_bmax_bits);  // ordered by kernel boundary

    int base = 0;
    #pragma unroll
    for (int j = 0; j < 8; j++) {
        const bool keep = (av[j] + Bmax >= amax);
        const unsigned int bal = __ballot_sync(0xffffffffu, keep);
        if (keep) {
            const int p = base + __popc(bal & ((1u << lane) - 1u));
            g_cand[n][p] = make_float2(av[j], __int_as_float(lane * 8 + j));
        }
        base += __popc(bal);
    }
    if (lane == 0) g_cnt[n] = base;
}

// ---------------------------------------------------------------------------
// Kernel 3: the sweep. grid = 2048 CTAs x 128 threads; warp = (row, 128-m
// slice). Reads only the tiny candidate list + bT rows; candidate LDG.128s
// are mutually independent -> high MLP, minimal instruction count.
// ---------------------------------------------------------------------------
__global__ void __launch_bounds__(128)
sweep_kernel(float* __restrict__ out) {
    const int tid   = threadIdx.x;
    const int lane  = tid & 31;
    const int wid   = tid >> 5;
    const int n     = blockIdx.x >> 1;
    const int slice = ((blockIdx.x & 1) << 2) | wid;  // 0..7

    const int cnt = g_cnt[n];                          // uniform LDG

    const float4* const bbase =
        reinterpret_cast<const float4*>(g_bT) + slice * 32 + lane;
    float4 acc = make_float4(-INFINITY, -INFINITY, -INFINITY, -INFINITY);

    for (int b = 0; b < cnt; b += 32) {
        const int lim = min(32, cnt - b);
        float2 p = make_float2(0.0f, 0.0f);
        if (lane < lim) p = g_cand[n][b + lane];       // one LDG.64 per lane
        for (int j = 0; j < lim; j++) {
            const float aj = __shfl_sync(0xffffffffu, p.x, j);
            const int   kj = __float_as_int(__shfl_sync(0xffffffffu, p.y, j));
            const float4 v = bbase[kj * (M_ / 4)];     // coalesced, independent
            acc.x = fmaxf(acc.x, aj + v.x);
            acc.y = fmaxf(acc.y, aj + v.y);
            acc.z = fmaxf(acc.z, aj + v.z);
            acc.w = fmaxf(acc.w, aj + v.w);
        }
    }

    reinterpret_cast<float4*>(out + n * M_)[slice * 32 + lane] = acc;
}

// ---------------------------------------------------------------------------
extern "C" void kernel_launch(void* const* d_in, const int* in_sizes, int n_in,
                              void* d_out, int out_size) {
    const float* x = (const float*)d_in[0];   // [N, K] fp32
    const float* w = (const float*)d_in[1];   // [M, K] fp32
    float* out     = (float*)d_out;           // [N, M] fp32

    (void)in_sizes; (void)n_in; (void)out_size;

    absT_kernel<<<dim3(M_ / 64, K_ / 64), 256>>>(w);
    candidates_kernel<<<N_ / 4, 128>>>(x);
    sweep_kernel<<<2 * N_, 128>>>(out);
}